// round 3
// baseline (speedup 1.0000x reference)
#include <cuda_runtime.h>
#include <math.h>
#include <stdint.h>

// ====================================================================
// PulseTrainSynth — B200/GB300 implementation
//   scan  -> phase prefix sum (fp64 accum)
//   noise -> 32-band dot product
//   setup -> threefry gumbel argmax -> resonator taps -> A^(2^k) tables
//   main  -> harmonic bank (Chebyshev sin recurrence) + env/noise mix
//   FIR   -> (1-A)(1+A^2)...(1+A^64) x  for resonators a,b then c
// ====================================================================

#define JAX_PARTITIONABLE 1   // flip to 0 if rel_err shows wrong tap index

#define T_LEN 65536
#define NCHN 8
#define NHARM 64
#define NBANDS 32
#define TWO_PI_F 6.283185307179586f

__device__ float g_phase[2 * T_LEN];
__device__ float g_noise[2 * T_LEN];
__device__ float g_v0[4 * T_LEN];
__device__ float g_v1[4 * T_LEN];
__device__ float g_vc0[2 * T_LEN];
__device__ float g_vc1[2 * T_LEN];

__device__ int   g_tdel[3][7][65];
__device__ float g_tcoef[3][7][65];

__constant__ float c_forder[8] = {0.f, 4.f, 3.f, 7.f, 5.f, 2.f, 6.f, 1.f};

// ------------------------- threefry2x32-20 --------------------------
__device__ __forceinline__ void threefry2x32(uint32_t k0, uint32_t k1,
                                             uint32_t c0, uint32_t c1,
                                             uint32_t* o0, uint32_t* o1)
{
    uint32_t ks2 = k0 ^ k1 ^ 0x1BD11BDAu;
    uint32_t x0 = c0 + k0;
    uint32_t x1 = c1 + k1;
#define TF_R(r) { x0 += x1; x1 = (x1 << (r)) | (x1 >> (32 - (r))); x1 ^= x0; }
    TF_R(13) TF_R(15) TF_R(26) TF_R(6)   x0 += k1;  x1 += ks2 + 1u;
    TF_R(17) TF_R(29) TF_R(16) TF_R(24)  x0 += ks2; x1 += k0 + 2u;
    TF_R(13) TF_R(15) TF_R(26) TF_R(6)   x0 += k0;  x1 += k1 + 3u;
    TF_R(17) TF_R(29) TF_R(16) TF_R(24)  x0 += k1;  x1 += ks2 + 4u;
    TF_R(13) TF_R(15) TF_R(26) TF_R(6)   x0 += ks2; x1 += k0 + 5u;
#undef TF_R
    *o0 = x0; *o1 = x1;
}

// i-th 32-bit word of jax random_bits(key, 32, (n,))
__device__ __forceinline__ uint32_t jax_bits(uint32_t k0, uint32_t k1, int i, int n)
{
#if JAX_PARTITIONABLE
    uint32_t o0, o1;
    threefry2x32(k0, k1, 0u, (uint32_t)i, &o0, &o1);
    return o0 ^ o1;
#else
    int half = (n + 1) >> 1;
    uint32_t o0, o1;
    if (i < half) {
        uint32_t c1 = (half + i < n) ? (uint32_t)(half + i) : 0u;  // pad slot
        threefry2x32(k0, k1, (uint32_t)i, c1, &o0, &o1);
        return o0;
    } else {
        int j = i - half;
        threefry2x32(k0, k1, (uint32_t)j, (uint32_t)i, &o0, &o1);
        return o1;
    }
#endif
}

__device__ __forceinline__ float jax_gumbel(uint32_t k0, uint32_t k1, int i, int n)
{
    uint32_t bits = jax_bits(k0, k1, i, n);
    float f = __uint_as_float((bits >> 9) | 0x3F800000u) - 1.0f;  // [0,1)
    const float tiny = 1.17549435e-38f;
    float u = fmaxf(tiny, f);   // uniform(tiny, 1)
    return -logf(-logf(u));
}

// ------------------------------ scan --------------------------------
__global__ void scan_kernel(const float* __restrict__ f0)
{
    int b = blockIdx.x;
    int tid = threadIdx.x;            // 1024 threads
    int lane = tid & 31, wid = tid >> 5;
    const float* f = f0 + (size_t)b * T_LEN;
    const int base = tid * 64;

    double s = 0.0;
    for (int i = 0; i < 64; i++) {
        float zf = (TWO_PI_F * f[base + i]) / 48000.0f;
        s += (double)zf;
    }
    double inc = s;
    #pragma unroll
    for (int off = 1; off < 32; off <<= 1) {
        double nv = __shfl_up_sync(0xffffffffu, inc, off);
        if (lane >= off) inc += nv;
    }
    __shared__ double wsums[32];
    if (lane == 31) wsums[wid] = inc;
    __syncthreads();
    if (wid == 0) {
        double w = wsums[lane];
        #pragma unroll
        for (int off = 1; off < 32; off <<= 1) {
            double nv = __shfl_up_sync(0xffffffffu, w, off);
            if (lane >= off) w += nv;
        }
        wsums[lane] = w;
    }
    __syncthreads();
    double run = inc - s + (wid ? wsums[wid - 1] : 0.0);   // exclusive prefix
    for (int i = 0; i < 64; i++) {
        float zf = (TWO_PI_F * f[base + i]) / 48000.0f;
        run += (double)zf;
        g_phase[(size_t)b * T_LEN + base + i] = (float)(run * 0.5);
    }
}

// ------------------------------ noise -------------------------------
__global__ void noise_kernel(const float* __restrict__ nba,
                             const float* __restrict__ nb)
{
    int b = blockIdx.y;
    int t = blockIdx.x * blockDim.x + threadIdx.x;
    float acc = 0.0f;
    #pragma unroll
    for (int n = 0; n < NBANDS; n++)
        acc = fmaf(nba[((size_t)(b * NBANDS + n)) * T_LEN + t],
                   nb[(size_t)n * T_LEN + t], acc);
    g_noise[(size_t)b * T_LEN + t] = acc;
}

// ------------------------------ setup -------------------------------
__global__ void setup_kernel(const float* __restrict__ logit_a, const float* __restrict__ fbg_a, const float* __restrict__ refl_a,
                             const float* __restrict__ logit_b, const float* __restrict__ fbg_b, const float* __restrict__ refl_b,
                             const float* __restrict__ logit_c, const float* __restrict__ fbg_c, const float* __restrict__ refl_c)
{
    __shared__ uint32_t skey[3][2];
    __shared__ float rv[128];
    __shared__ int   ri[128];
    __shared__ int   s_idx[3];
    __shared__ float sc1[3], sc2[3];
    __shared__ int   sD1[3], sD2[3];
    __shared__ float sP[3][65];
    __shared__ float sQ[3][65];

    int tid = threadIdx.x;   // 128 threads

    if (tid == 0) {
#if JAX_PARTITIONABLE
        for (int j = 0; j < 3; j++) {
            uint32_t o0, o1;
            threefry2x32(0u, 42u, 0u, (uint32_t)j, &o0, &o1);
            skey[j][0] = o0; skey[j][1] = o1;
        }
#else
        uint32_t a0, a1, b0v, b1v, c0v, c1v;
        threefry2x32(0u, 42u, 0u, 3u, &a0, &a1);
        threefry2x32(0u, 42u, 1u, 4u, &b0v, &b1v);
        threefry2x32(0u, 42u, 2u, 5u, &c0v, &c1v);
        // flat = [a0,b0,c0,a1,b1,c1] reshaped (3,2)
        skey[0][0] = a0;  skey[0][1] = b0v;
        skey[1][0] = c0v; skey[1][1] = a1;
        skey[2][0] = b1v; skey[2][1] = c1v;
#endif
    }
    __syncthreads();

    const float* logits[3] = {logit_a, logit_b, logit_c};
    const int    Ls[3]     = {85, 85, 8};

    for (int r = 0; r < 3; r++) {
        int L = Ls[r];
        float score = -3.0e38f;
        if (tid < L)
            score = logits[r][tid] + jax_gumbel(skey[r][0], skey[r][1], tid, L);
        rv[tid] = score; ri[tid] = tid;
        __syncthreads();
        for (int s = 64; s > 0; s >>= 1) {
            if (tid < s) {
                float ov = rv[tid + s]; int oi = ri[tid + s];
                if (ov > rv[tid] || (ov == rv[tid] && oi < ri[tid])) {
                    rv[tid] = ov; ri[tid] = oi;
                }
            }
            __syncthreads();
        }
        if (tid == 0) s_idx[r] = ri[0];
        __syncthreads();
    }

    if (tid == 0) {
        const float* refls[3] = {refl_a, refl_b, refl_c};
        const float* fbs[3]   = {fbg_a, fbg_b, fbg_c};
        const int    mind[3]  = {40, 40, 32};
        for (int r = 0; r < 3; r++) {
            float r0 = refls[r][0], r1 = refls[r][1];
            if (r == 2) {   // lowpass: sigmoid
                r0 = 1.0f / (1.0f + expf(-r0));
                r1 = 1.0f / (1.0f + expf(-r1));
            } else {        // tanh
                r0 = tanhf(r0); r1 = tanhf(r1);
            }
            float k1v = tanhf(r0);     // resonant_activation(x, 0) = tanh(x)
            float k2v = tanhf(r1);
            float a1 = k1v * (1.0f - k2v);
            float a2 = fminf(0.999f, fmaxf(-0.999f, k2v));
            float bnd = 0.999f - fabsf(a2);
            a1 = fminf(bnd, fmaxf(-bnd, a1));
            float g = powf(1.0f / (1.0f + expf(-fbs[r][0])), 0.45f);
            int L = Ls[r];
            int idx = s_idx[r];
            sc1[r] = a1 * g;
            sc2[r] = a2 * g;
            sD1[r] = mind[r] + idx + 1;
            sD2[r] = mind[r] + ((idx + 1) % L) + 1;
        }
    }
    __syncthreads();

    // stage 0: out = in - (c1 z^-D1 + c2 z^-D2) in ; polynomial P = A
    if (tid < 3) {
        int r = tid;
        g_tdel[r][0][0] = sD1[r]; g_tcoef[r][0][0] = -sc1[r];
        g_tdel[r][0][1] = sD2[r]; g_tcoef[r][0][1] = -sc2[r];
        sP[r][0] = sc1[r]; sP[r][1] = sc2[r];
    }
    __syncthreads();

    // stages k=1..6: P_k = P_{k-1} * P_{k-1}  (A^(2^k)); out = in + P_k * in
    for (int k = 1; k < 7; k++) {
        int n = 1 << k;
        int m = n >> 1;
        for (int idx = tid; idx < 3 * (n + 1); idx += blockDim.x) {
            int r = idx / (n + 1), i = idx % (n + 1);
            int lo = (i - m > 0) ? (i - m) : 0;
            int hi = (m < i) ? m : i;
            float s = 0.0f;
            for (int a = lo; a <= hi; a++) s += sP[r][a] * sP[r][i - a];
            sQ[r][i] = s;
            g_tcoef[r][k][i] = s;
            g_tdel[r][k][i] = n * sD1[r] + i * (sD2[r] - sD1[r]);
        }
        __syncthreads();
        for (int idx = tid; idx < 3 * (n + 1); idx += blockDim.x) {
            int r = idx / (n + 1), i = idx % (n + 1);
            sP[r][i] = sQ[r][i];
        }
        __syncthreads();
    }
}

// ------------------------------ main --------------------------------
__global__ void main_kernel(const float* __restrict__ amps,
                            const float* __restrict__ fm_in,
                            const float* __restrict__ cps,
                            const float* __restrict__ nps,
                            const float* __restrict__ npg_in,
                            const float* __restrict__ fng_in)
{
    int b = blockIdx.y;
    int t = blockIdx.x * blockDim.x + threadIdx.x;
    size_t bt = (size_t)b * T_LEN + t;

    float phase = g_phase[bt];
    float fm    = fm_in[bt];
    float noise = g_noise[bt];
    float npg   = npg_in[bt];
    float fng   = fng_in[bt];
    float na    = nps[((size_t)(b * 2)) * T_LEN + t];
    float nbv   = nps[((size_t)(b * 2 + 1)) * T_LEN + t];

    float nph  = fmodf(phase, TWO_PI_F);
    float nenv = (1.0f - expf(-na * nph)) * expf(-nbv * nph);
    float noise_bursts = noise * nenv * npg;
    float flow = noise * fng * 0.3f;
    float turb = noise * (npg + fng) * 0.7f;

    float bankA = 4.0f * (noise_bursts + flow);
    float bankB = bankA;

    #pragma unroll 1
    for (int c = 0; c < NCHN; c++) {
        float ang = c_forder[c] * (TWO_PI_F / 8.0f);
        float cph = fmodf(phase + ang, TWO_PI_F);
        float hp  = powf(cph / TWO_PI_F, fm) * TWO_PI_F;
        float sv, cv;
        sincosf(hp, &sv, &cv);
        float twoC = 2.0f * cv;

        const float* ap = amps + ((size_t)(b * NCHN + c) * NHARM) * T_LEN + t;
        float sm1 = 0.0f, scur = sv, acc = 0.0f;
        #pragma unroll
        for (int h = 0; h < NHARM; h++) {
            acc = fmaf(ap[(size_t)h * T_LEN], scur, acc);
            float snxt = fmaf(twoC, scur, -sm1);
            sm1 = scur; scur = snxt;
        }
        float harm = -acc;

        float alpha = cps[((size_t)(b * 16 + c)) * T_LEN + t];
        float beta  = cps[((size_t)(b * 16 + 8 + c)) * T_LEN + t];
        float env = (1.0f - expf(-alpha * cph)) * expf(-beta * cph);
        float he = harm * env * 10.0f;
        float contrib = he * (1.0f + turb);
        if (c < 4) bankA += contrib; else bankB += contrib;
    }

    g_v0[((size_t)(b * 2 + 0)) * T_LEN + t] = bankA;
    g_v0[((size_t)(b * 2 + 1)) * T_LEN + t] = bankB;
}

// ------------------------------ FIR ---------------------------------
__global__ void fir_kernel(const float* __restrict__ in, float* __restrict__ out,
                           int stage, int resbase, int rmask)
{
    int row = blockIdx.y;
    int res = resbase + (row & rmask);
    int t = blockIdx.x * blockDim.x + threadIdx.x;
    const float* x = in + (size_t)row * T_LEN;

    float acc = x[t];
    int nt = (stage == 0) ? 2 : ((1 << stage) + 1);
    for (int i = 0; i < nt; i++) {
        int d = g_tdel[res][stage][i];
        if (t >= d) acc = fmaf(g_tcoef[res][stage][i], x[t - d], acc);
    }
    out[(size_t)row * T_LEN + t] = acc;
}

__global__ void combine_kernel(const float* __restrict__ in)
{
    int b = blockIdx.y;
    int t = blockIdx.x * blockDim.x + threadIdx.x;
    g_vc0[(size_t)b * T_LEN + t] =
        in[((size_t)(2 * b)) * T_LEN + t] + in[((size_t)(2 * b + 1)) * T_LEN + t];
}

// ----------------------------- launch -------------------------------
extern "C" void kernel_launch(void* const* d_in, const int* in_sizes, int n_in,
                              void* d_out, int out_size)
{
    (void)in_sizes; (void)n_in; (void)out_size;
    const float* f0   = (const float*)d_in[0];
    const float* amps = (const float*)d_in[1];
    const float* fm   = (const float*)d_in[2];
    const float* cps  = (const float*)d_in[4];
    const float* nba  = (const float*)d_in[5];
    const float* nps  = (const float*)d_in[6];
    const float* npg  = (const float*)d_in[7];
    const float* fng  = (const float*)d_in[8];
    const float* nb   = (const float*)d_in[9];
    float* out = (float*)d_out;

    scan_kernel<<<2, 1024>>>(f0);
    dim3 g2(T_LEN / 256, 2);
    noise_kernel<<<g2, 256>>>(nba, nb);
    setup_kernel<<<1, 128>>>((const float*)d_in[10], (const float*)d_in[11], (const float*)d_in[12],
                             (const float*)d_in[13], (const float*)d_in[14], (const float*)d_in[15],
                             (const float*)d_in[16], (const float*)d_in[17], (const float*)d_in[18]);
    main_kernel<<<g2, 256>>>(amps, fm, cps, nps, npg, fng);

    float *v0, *v1, *vc0, *vc1;
    cudaGetSymbolAddress((void**)&v0, g_v0);
    cudaGetSymbolAddress((void**)&v1, g_v1);
    cudaGetSymbolAddress((void**)&vc0, g_vc0);
    cudaGetSymbolAddress((void**)&vc1, g_vc1);

    // resonators a,b: 4 rows, res = row & 1
    dim3 gab(T_LEN / 256, 4);
    float* cur = v0;
    float* nxt = v1;
    for (int s = 0; s < 7; s++) {
        fir_kernel<<<gab, 256>>>(cur, nxt, s, 0, 1);
        float* tmp = cur; cur = nxt; nxt = tmp;
    }
    // cur now holds resonated a,b (in v1 after 7 stages)

    combine_kernel<<<g2, 256>>>(cur);

    // resonator c: 2 rows, res = 2; last stage writes d_out
    float* ccur = vc0;
    float* cnxt = vc1;
    for (int s = 0; s < 7; s++) {
        float* o = (s == 6) ? out : cnxt;
        fir_kernel<<<g2, 256>>>(ccur, o, s, 2, 0);
        float* tmp = ccur; ccur = o; cnxt = tmp;
    }
}

// round 4
// speedup vs baseline: 1.2820x; 1.2820x over previous
#include <cuda_runtime.h>
#include <math.h>
#include <stdint.h>

// ====================================================================
// PulseTrainSynth — R3
//   prep  -> phase prefix sum (blocks 0,1) + resonator setup (block 2)
//   noise -> 32-band dot product
//   main  -> harmonic bank, grid.z splits cylinders 0-3 / 4-7
//   FIR   -> radix-4 Neumann factorization, 4 smem-tiled passes per chain
// ====================================================================

#define T_LEN 65536
#define NCHN 8
#define NHARM 64
#define NBANDS 32
#define TWO_PI_F 6.283185307179586f

#define CHUNK 2048
#define HALOMAX 8192
#define FIR_THREADS 512
#define MAXTAPS 100

__device__ float g_phase[2 * T_LEN];
__device__ float g_noise[2 * T_LEN];
__device__ float g_v0[4 * T_LEN];
__device__ float g_v1[4 * T_LEN];
__device__ float g_vc0[2 * T_LEN];
__device__ float g_vc1[2 * T_LEN];

// pass tables: [chain][pass][tap]
__device__ float g_pcoef[3][4][MAXTAPS];
__device__ int   g_pdel[3][4][MAXTAPS];
__device__ int   g_phalo[3][4];

__constant__ int   c_pcnt[4] = {9, 27, 99, 65};
__constant__ float c_forder[8] = {0.f, 4.f, 3.f, 7.f, 5.f, 2.f, 6.f, 1.f};

// ------------------------- threefry2x32-20 --------------------------
__device__ __forceinline__ void threefry2x32(uint32_t k0, uint32_t k1,
                                             uint32_t c0, uint32_t c1,
                                             uint32_t* o0, uint32_t* o1)
{
    uint32_t ks2 = k0 ^ k1 ^ 0x1BD11BDAu;
    uint32_t x0 = c0 + k0;
    uint32_t x1 = c1 + k1;
#define TF_R(r) { x0 += x1; x1 = (x1 << (r)) | (x1 >> (32 - (r))); x1 ^= x0; }
    TF_R(13) TF_R(15) TF_R(26) TF_R(6)   x0 += k1;  x1 += ks2 + 1u;
    TF_R(17) TF_R(29) TF_R(16) TF_R(24)  x0 += ks2; x1 += k0 + 2u;
    TF_R(13) TF_R(15) TF_R(26) TF_R(6)   x0 += k0;  x1 += k1 + 3u;
    TF_R(17) TF_R(29) TF_R(16) TF_R(24)  x0 += k1;  x1 += ks2 + 4u;
    TF_R(13) TF_R(15) TF_R(26) TF_R(6)   x0 += ks2; x1 += k0 + 5u;
#undef TF_R
    *o0 = x0; *o1 = x1;
}

__device__ __forceinline__ float jax_gumbel(uint32_t k0, uint32_t k1, int i)
{
    uint32_t o0, o1;
    threefry2x32(k0, k1, 0u, (uint32_t)i, &o0, &o1);
    uint32_t bits = o0 ^ o1;
    float f = __uint_as_float((bits >> 9) | 0x3F800000u) - 1.0f;  // [0,1)
    const float tiny = 1.17549435e-38f;
    float u = fmaxf(tiny, f);
    return -logf(-logf(u));
}

// --------------------- prep: scan + setup ---------------------------
__global__ void prep_kernel(const float* __restrict__ f0,
    const float* __restrict__ logit_a, const float* __restrict__ fbg_a, const float* __restrict__ refl_a,
    const float* __restrict__ logit_b, const float* __restrict__ fbg_b, const float* __restrict__ refl_b,
    const float* __restrict__ logit_c, const float* __restrict__ fbg_c, const float* __restrict__ refl_c)
{
    int tid = threadIdx.x;               // 1024 threads
    int lane = tid & 31, wid = tid >> 5;

    if (blockIdx.x < 2) {
        // ---------- phase prefix sum (fp64 accumulation) ----------
        int b = blockIdx.x;
        const float* f = f0 + (size_t)b * T_LEN;
        const int base = tid * 64;
        double s = 0.0;
        for (int i = 0; i < 64; i++) {
            float zf = (TWO_PI_F * f[base + i]) / 48000.0f;
            s += (double)zf;
        }
        double inc = s;
        #pragma unroll
        for (int off = 1; off < 32; off <<= 1) {
            double nv = __shfl_up_sync(0xffffffffu, inc, off);
            if (lane >= off) inc += nv;
        }
        __shared__ double wsums[32];
        if (lane == 31) wsums[wid] = inc;
        __syncthreads();
        if (wid == 0) {
            double w = wsums[lane];
            #pragma unroll
            for (int off = 1; off < 32; off <<= 1) {
                double nv = __shfl_up_sync(0xffffffffu, w, off);
                if (lane >= off) w += nv;
            }
            wsums[lane] = w;
        }
        __syncthreads();
        double run = inc - s + (wid ? wsums[wid - 1] : 0.0);
        for (int i = 0; i < 64; i++) {
            float zf = (TWO_PI_F * f[base + i]) / 48000.0f;
            run += (double)zf;
            g_phase[(size_t)b * T_LEN + base + i] = (float)(run * 0.5);
        }
        return;
    }

    // ------------------------- setup (block 2) ----------------------
    __shared__ uint32_t skey[3][2];
    __shared__ float rv[128];
    __shared__ int   ri[128];
    __shared__ int   s_idx[3];
    __shared__ float sc1, sc2;
    __shared__ int   sD1, sD2;
    // polynomial workspace: A^1,A^2,A^3,A^4,A^8,A^12,A^16,A^32,A^48,A^64
    __shared__ float P[10][65];

    if (tid == 0) {
        for (int j = 0; j < 3; j++) {
            uint32_t o0, o1;
            threefry2x32(0u, 42u, 0u, (uint32_t)j, &o0, &o1);
            skey[j][0] = o0; skey[j][1] = o1;
        }
    }
    __syncthreads();

    const float* logits[3] = {logit_a, logit_b, logit_c};
    const float* refls[3]  = {refl_a, refl_b, refl_c};
    const float* fbs[3]    = {fbg_a, fbg_b, fbg_c};
    const int    Ls[3]     = {85, 85, 8};
    const int    mind[3]   = {40, 40, 32};

    for (int r = 0; r < 3; r++) {
        int L = Ls[r];
        if (tid < 128) {
            float score = -3.0e38f;
            if (tid < L)
                score = logits[r][tid] + jax_gumbel(skey[r][0], skey[r][1], tid);
            rv[tid] = score; ri[tid] = tid;
        }
        __syncthreads();
        for (int s = 64; s > 0; s >>= 1) {
            if (tid < s) {
                float ov = rv[tid + s]; int oi = ri[tid + s];
                if (ov > rv[tid] || (ov == rv[tid] && oi < ri[tid])) {
                    rv[tid] = ov; ri[tid] = oi;
                }
            }
            __syncthreads();
        }
        if (tid == 0) s_idx[r] = ri[0];
        __syncthreads();
    }

    // sizes of the 10 stored polynomials
    const int psz[10] = {2, 3, 4, 5, 9, 13, 17, 33, 49, 65};
    // conv plan: dst <- a (*) b
    const int plan[9][3] = {
        {1, 0, 0},   // A^2  = A*A
        {2, 0, 1},   // A^3  = A*A^2
        {3, 1, 1},   // A^4  = A^2*A^2
        {4, 3, 3},   // A^8
        {5, 3, 4},   // A^12 = A^4*A^8
        {6, 4, 4},   // A^16
        {7, 6, 6},   // A^32
        {8, 6, 7},   // A^48 = A^16*A^32
        {9, 7, 7},   // A^64
    };

    for (int r = 0; r < 3; r++) {
        if (tid == 0) {
            float r0 = refls[r][0], r1 = refls[r][1];
            if (r == 2) { r0 = 1.0f / (1.0f + expf(-r0)); r1 = 1.0f / (1.0f + expf(-r1)); }
            else        { r0 = tanhf(r0); r1 = tanhf(r1); }
            float k1v = tanhf(r0);
            float k2v = tanhf(r1);
            float a1 = k1v * (1.0f - k2v);
            float a2 = fminf(0.999f, fmaxf(-0.999f, k2v));
            float bnd = 0.999f - fabsf(a2);
            a1 = fminf(bnd, fmaxf(-bnd, a1));
            float g = powf(1.0f / (1.0f + expf(-fbs[r][0])), 0.45f);
            int L = Ls[r];
            int idx = s_idx[r];
            sc1 = a1 * g;
            sc2 = a2 * g;
            sD1 = mind[r] + idx + 1;
            sD2 = mind[r] + ((idx + 1) % L) + 1;
            P[0][0] = sc1; P[0][1] = sc2;
        }
        __syncthreads();

        for (int cv = 0; cv < 9; cv++) {
            int d = plan[cv][0], a = plan[cv][1], bb = plan[cv][2];
            int la = psz[a], lb = psz[bb], ld = la + lb - 1;
            if (tid < ld) {
                int i = tid;
                int lo = i - (lb - 1); if (lo < 0) lo = 0;
                int hi = (la - 1 < i) ? la - 1 : i;
                float s = 0.0f;
                for (int q = lo; q <= hi; q++) s += P[a][q] * P[bb][i - q];
                // careful: in-place hazards avoided (dst always a new slot)
                P[d][i] = s;
            }
            __syncthreads();
        }

        if (tid == 0) {
            // pass j-sets and signs
            const int   js[4][3]  = {{1,2,3},{4,8,12},{16,32,48},{64,0,0}};
            const int   nj[4]     = {3, 3, 3, 1};
            // polynomial slot for power j
            // j:      1  2  3  4  8  12 16 32 48 64
            // slot:   0  1  2  3  4  5  6  7  8  9
            int D1 = sD1, D2 = sD2;
            for (int p = 0; p < 4; p++) {
                int ofs = 0, maxd = 0;
                for (int m = 0; m < nj[p]; m++) {
                    int j = js[p][m];
                    int slot;
                    switch (j) {
                        case 1: slot = 0; break; case 2: slot = 1; break;
                        case 3: slot = 2; break; case 4: slot = 3; break;
                        case 8: slot = 4; break; case 12: slot = 5; break;
                        case 16: slot = 6; break; case 32: slot = 7; break;
                        case 48: slot = 8; break; default: slot = 9; break;
                    }
                    float sgn = (j & 1) ? -1.0f : 1.0f;
                    for (int i = 0; i <= j; i++) {
                        int d = j * D1 + i * (D2 - D1);
                        g_pcoef[r][p][ofs] = sgn * P[slot][i];
                        g_pdel[r][p][ofs] = d;
                        if (d > maxd) maxd = d;
                        ofs++;
                    }
                }
                g_phalo[r][p] = (maxd + 511) & ~511;
            }
        }
        __syncthreads();
    }
}

// ------------------------------ noise -------------------------------
__global__ void noise_kernel(const float* __restrict__ nba,
                             const float* __restrict__ nb)
{
    int b = blockIdx.y;
    int t = blockIdx.x * blockDim.x + threadIdx.x;
    float acc = 0.0f;
    #pragma unroll
    for (int n = 0; n < NBANDS; n++)
        acc = fmaf(nba[((size_t)(b * NBANDS + n)) * T_LEN + t],
                   nb[(size_t)n * T_LEN + t], acc);
    g_noise[(size_t)b * T_LEN + t] = acc;
}

// ------------------------------ main --------------------------------
__global__ void __launch_bounds__(256) main_kernel(
                            const float* __restrict__ amps,
                            const float* __restrict__ fm_in,
                            const float* __restrict__ cps,
                            const float* __restrict__ nps,
                            const float* __restrict__ npg_in,
                            const float* __restrict__ fng_in)
{
    int b = blockIdx.y;
    int z = blockIdx.z;               // 0: cylinders 0-3 -> bankA, 1: 4-7 -> bankB
    int t = blockIdx.x * blockDim.x + threadIdx.x;
    size_t bt = (size_t)b * T_LEN + t;

    float phase = g_phase[bt];
    float fm    = fm_in[bt];
    float noise = g_noise[bt];
    float npg   = npg_in[bt];
    float fng   = fng_in[bt];
    float na    = nps[((size_t)(b * 2)) * T_LEN + t];
    float nbv   = nps[((size_t)(b * 2 + 1)) * T_LEN + t];

    float nph  = fmodf(phase, TWO_PI_F);
    float nenv = (1.0f - __expf(-na * nph)) * __expf(-nbv * nph);
    float noise_bursts = noise * nenv * npg;
    float flow = noise * fng * 0.3f;
    float turb1 = 1.0f + noise * (npg + fng) * 0.7f;

    float bank = 4.0f * (noise_bursts + flow);

    #pragma unroll 1
    for (int c4 = 0; c4 < 4; c4++) {
        int c = z * 4 + c4;
        float ang = c_forder[c] * (TWO_PI_F / 8.0f);
        float cph = fmodf(phase + ang, TWO_PI_F);
        float hp  = __powf(cph * (1.0f / TWO_PI_F), fm) * TWO_PI_F;
        float sv, cv;
        sincosf(hp, &sv, &cv);
        float twoC = 2.0f * cv;

        const float* ap = amps + ((size_t)(b * NCHN + c) * NHARM) * T_LEN + t;
        float sm1 = 0.0f, scur = sv, acc = 0.0f;
        #pragma unroll
        for (int h = 0; h < NHARM; h++) {
            acc = fmaf(__ldcs(ap + (size_t)h * T_LEN), scur, acc);
            float snxt = fmaf(twoC, scur, -sm1);
            sm1 = scur; scur = snxt;
        }
        float harm = -acc;

        float alpha = cps[((size_t)(b * 16 + c)) * T_LEN + t];
        float beta  = cps[((size_t)(b * 16 + 8 + c)) * T_LEN + t];
        float env = (1.0f - __expf(-alpha * cph)) * __expf(-beta * cph);
        bank = fmaf(harm * env * 10.0f, turb1, bank);
    }

    g_v0[((size_t)(b * 2 + z)) * T_LEN + t] = bank;
}

// -------------------------- FIR (smem-tiled) ------------------------
// chainmode 0: rows=4, chain=row&1, plain input rows
// chainmode 1: rows=2, chain=2; if pass==0, input = in[2*row] + in[2*row+1]
__global__ void __launch_bounds__(FIR_THREADS) fir_pass_kernel(
    const float* __restrict__ in, float* __restrict__ out,
    int pass, int chainmode)
{
    __shared__ float sx[HALOMAX + CHUNK];
    __shared__ float sc[MAXTAPS];
    __shared__ int   sd[MAXTAPS];

    int tid = threadIdx.x;
    int row = blockIdx.y;
    int chain = chainmode ? 2 : (row & 1);
    int cnt = c_pcnt[pass];
    int halo = g_phalo[chain][pass];

    for (int i = tid; i < cnt; i += FIR_THREADS) {
        sc[i] = g_pcoef[chain][pass][i];
        sd[i] = g_pdel[chain][pass][i];
    }

    int base = blockIdx.x * CHUNK;
    int nload = halo + CHUNK;
    if (chainmode && pass == 0) {
        const float* xa = in + ((size_t)(2 * row)) * T_LEN;
        const float* xb = in + ((size_t)(2 * row + 1)) * T_LEN;
        for (int k = tid; k < nload; k += FIR_THREADS) {
            int g = base - halo + k;
            sx[k] = (g >= 0) ? (xa[g] + xb[g]) : 0.0f;
        }
    } else {
        const float* x = in + (size_t)row * T_LEN;
        for (int k = tid; k < nload; k += FIR_THREADS) {
            int g = base - halo + k;
            sx[k] = (g >= 0) ? x[g] : 0.0f;
        }
    }
    __syncthreads();

    #pragma unroll
    for (int o = 0; o < CHUNK / FIR_THREADS; o++) {
        int li = o * FIR_THREADS + tid;       // local output index in chunk
        float acc = sx[halo + li];
        for (int i = 0; i < cnt; i++)
            acc = fmaf(sc[i], sx[halo + li - sd[i]], acc);
        out[(size_t)row * T_LEN + base + li] = acc;
    }
}

// ----------------------------- launch -------------------------------
extern "C" void kernel_launch(void* const* d_in, const int* in_sizes, int n_in,
                              void* d_out, int out_size)
{
    (void)in_sizes; (void)n_in; (void)out_size;
    const float* f0   = (const float*)d_in[0];
    const float* amps = (const float*)d_in[1];
    const float* fm   = (const float*)d_in[2];
    const float* cps  = (const float*)d_in[4];
    const float* nba  = (const float*)d_in[5];
    const float* nps  = (const float*)d_in[6];
    const float* npg  = (const float*)d_in[7];
    const float* fng  = (const float*)d_in[8];
    const float* nb   = (const float*)d_in[9];
    float* out = (float*)d_out;

    prep_kernel<<<3, 1024>>>(f0,
        (const float*)d_in[10], (const float*)d_in[11], (const float*)d_in[12],
        (const float*)d_in[13], (const float*)d_in[14], (const float*)d_in[15],
        (const float*)d_in[16], (const float*)d_in[17], (const float*)d_in[18]);

    dim3 g2(T_LEN / 256, 2);
    noise_kernel<<<g2, 256>>>(nba, nb);

    dim3 gm(T_LEN / 256, 2, 2);
    main_kernel<<<gm, 256>>>(amps, fm, cps, nps, npg, fng);

    float *v0, *v1, *vc0, *vc1;
    cudaGetSymbolAddress((void**)&v0, g_v0);
    cudaGetSymbolAddress((void**)&v1, g_v1);
    cudaGetSymbolAddress((void**)&vc0, g_vc0);
    cudaGetSymbolAddress((void**)&vc1, g_vc1);

    // chains a,b: 4 rows, 4 passes  v0 -> v1 -> v0 -> v1 -> v0
    dim3 gab(T_LEN / CHUNK, 4);
    fir_pass_kernel<<<gab, FIR_THREADS>>>(v0, v1, 0, 0);
    fir_pass_kernel<<<gab, FIR_THREADS>>>(v1, v0, 1, 0);
    fir_pass_kernel<<<gab, FIR_THREADS>>>(v0, v1, 2, 0);
    fir_pass_kernel<<<gab, FIR_THREADS>>>(v1, v0, 3, 0);

    // chain c: 2 rows, pass0 fuses the pairwise sum; last pass writes d_out
    dim3 gc(T_LEN / CHUNK, 2);
    fir_pass_kernel<<<gc, FIR_THREADS>>>(v0, vc0, 0, 1);
    fir_pass_kernel<<<gc, FIR_THREADS>>>(vc0, vc1, 1, 1);
    fir_pass_kernel<<<gc, FIR_THREADS>>>(vc1, vc0, 2, 1);
    fir_pass_kernel<<<gc, FIR_THREADS>>>(vc0, out, 3, 1);
}

// round 5
// speedup vs baseline: 1.2865x; 1.0035x over previous
#include <cuda_runtime.h>
#include <math.h>
#include <stdint.h>

// ====================================================================
// PulseTrainSynth — R3
//   prep  -> phase prefix sum (blocks 0,1) + resonator setup (block 2)
//   noise -> 32-band dot product
//   main  -> harmonic bank, grid.z splits cylinders 0-3 / 4-7
//   FIR   -> radix-4 Neumann factorization, 4 smem-tiled passes per chain
// ====================================================================

#define T_LEN 65536
#define NCHN 8
#define NHARM 64
#define NBANDS 32
#define TWO_PI_F 6.283185307179586f

#define CHUNK 2048
#define HALOMAX 8192
#define FIR_THREADS 512
#define MAXTAPS 100

__device__ float g_phase[2 * T_LEN];
__device__ float g_noise[2 * T_LEN];
__device__ float g_v0[4 * T_LEN];
__device__ float g_v1[4 * T_LEN];
__device__ float g_vc0[2 * T_LEN];
__device__ float g_vc1[2 * T_LEN];

// pass tables: [chain][pass][tap]
__device__ float g_pcoef[3][4][MAXTAPS];
__device__ int   g_pdel[3][4][MAXTAPS];
__device__ int   g_phalo[3][4];

__constant__ int   c_pcnt[4] = {9, 27, 99, 65};
__constant__ float c_forder[8] = {0.f, 4.f, 3.f, 7.f, 5.f, 2.f, 6.f, 1.f};

// ------------------------- threefry2x32-20 --------------------------
__device__ __forceinline__ void threefry2x32(uint32_t k0, uint32_t k1,
                                             uint32_t c0, uint32_t c1,
                                             uint32_t* o0, uint32_t* o1)
{
    uint32_t ks2 = k0 ^ k1 ^ 0x1BD11BDAu;
    uint32_t x0 = c0 + k0;
    uint32_t x1 = c1 + k1;
#define TF_R(r) { x0 += x1; x1 = (x1 << (r)) | (x1 >> (32 - (r))); x1 ^= x0; }
    TF_R(13) TF_R(15) TF_R(26) TF_R(6)   x0 += k1;  x1 += ks2 + 1u;
    TF_R(17) TF_R(29) TF_R(16) TF_R(24)  x0 += ks2; x1 += k0 + 2u;
    TF_R(13) TF_R(15) TF_R(26) TF_R(6)   x0 += k0;  x1 += k1 + 3u;
    TF_R(17) TF_R(29) TF_R(16) TF_R(24)  x0 += k1;  x1 += ks2 + 4u;
    TF_R(13) TF_R(15) TF_R(26) TF_R(6)   x0 += ks2; x1 += k0 + 5u;
#undef TF_R
    *o0 = x0; *o1 = x1;
}

__device__ __forceinline__ float jax_gumbel(uint32_t k0, uint32_t k1, int i)
{
    uint32_t o0, o1;
    threefry2x32(k0, k1, 0u, (uint32_t)i, &o0, &o1);
    uint32_t bits = o0 ^ o1;
    float f = __uint_as_float((bits >> 9) | 0x3F800000u) - 1.0f;  // [0,1)
    const float tiny = 1.17549435e-38f;
    float u = fmaxf(tiny, f);
    return -logf(-logf(u));
}

// --------------------- prep: scan + setup ---------------------------
__global__ void prep_kernel(const float* __restrict__ f0,
    const float* __restrict__ logit_a, const float* __restrict__ fbg_a, const float* __restrict__ refl_a,
    const float* __restrict__ logit_b, const float* __restrict__ fbg_b, const float* __restrict__ refl_b,
    const float* __restrict__ logit_c, const float* __restrict__ fbg_c, const float* __restrict__ refl_c)
{
    int tid = threadIdx.x;               // 1024 threads
    int lane = tid & 31, wid = tid >> 5;

    if (blockIdx.x < 2) {
        // ---------- phase prefix sum (fp64 accumulation) ----------
        int b = blockIdx.x;
        const float* f = f0 + (size_t)b * T_LEN;
        const int base = tid * 64;
        double s = 0.0;
        for (int i = 0; i < 64; i++) {
            float zf = (TWO_PI_F * f[base + i]) / 48000.0f;
            s += (double)zf;
        }
        double inc = s;
        #pragma unroll
        for (int off = 1; off < 32; off <<= 1) {
            double nv = __shfl_up_sync(0xffffffffu, inc, off);
            if (lane >= off) inc += nv;
        }
        __shared__ double wsums[32];
        if (lane == 31) wsums[wid] = inc;
        __syncthreads();
        if (wid == 0) {
            double w = wsums[lane];
            #pragma unroll
            for (int off = 1; off < 32; off <<= 1) {
                double nv = __shfl_up_sync(0xffffffffu, w, off);
                if (lane >= off) w += nv;
            }
            wsums[lane] = w;
        }
        __syncthreads();
        double run = inc - s + (wid ? wsums[wid - 1] : 0.0);
        for (int i = 0; i < 64; i++) {
            float zf = (TWO_PI_F * f[base + i]) / 48000.0f;
            run += (double)zf;
            g_phase[(size_t)b * T_LEN + base + i] = (float)(run * 0.5);
        }
        return;
    }

    // ------------------------- setup (block 2) ----------------------
    __shared__ uint32_t skey[3][2];
    __shared__ float rv[128];
    __shared__ int   ri[128];
    __shared__ int   s_idx[3];
    __shared__ float sc1, sc2;
    __shared__ int   sD1, sD2;
    // polynomial workspace: A^1,A^2,A^3,A^4,A^8,A^12,A^16,A^32,A^48,A^64
    __shared__ float P[10][65];

    if (tid == 0) {
        for (int j = 0; j < 3; j++) {
            uint32_t o0, o1;
            threefry2x32(0u, 42u, 0u, (uint32_t)j, &o0, &o1);
            skey[j][0] = o0; skey[j][1] = o1;
        }
    }
    __syncthreads();

    const float* logits[3] = {logit_a, logit_b, logit_c};
    const float* refls[3]  = {refl_a, refl_b, refl_c};
    const float* fbs[3]    = {fbg_a, fbg_b, fbg_c};
    const int    Ls[3]     = {85, 85, 8};
    const int    mind[3]   = {40, 40, 32};

    for (int r = 0; r < 3; r++) {
        int L = Ls[r];
        if (tid < 128) {
            float score = -3.0e38f;
            if (tid < L)
                score = logits[r][tid] + jax_gumbel(skey[r][0], skey[r][1], tid);
            rv[tid] = score; ri[tid] = tid;
        }
        __syncthreads();
        for (int s = 64; s > 0; s >>= 1) {
            if (tid < s) {
                float ov = rv[tid + s]; int oi = ri[tid + s];
                if (ov > rv[tid] || (ov == rv[tid] && oi < ri[tid])) {
                    rv[tid] = ov; ri[tid] = oi;
                }
            }
            __syncthreads();
        }
        if (tid == 0) s_idx[r] = ri[0];
        __syncthreads();
    }

    // sizes of the 10 stored polynomials
    const int psz[10] = {2, 3, 4, 5, 9, 13, 17, 33, 49, 65};
    // conv plan: dst <- a (*) b
    const int plan[9][3] = {
        {1, 0, 0},   // A^2  = A*A
        {2, 0, 1},   // A^3  = A*A^2
        {3, 1, 1},   // A^4  = A^2*A^2
        {4, 3, 3},   // A^8
        {5, 3, 4},   // A^12 = A^4*A^8
        {6, 4, 4},   // A^16
        {7, 6, 6},   // A^32
        {8, 6, 7},   // A^48 = A^16*A^32
        {9, 7, 7},   // A^64
    };

    for (int r = 0; r < 3; r++) {
        if (tid == 0) {
            float r0 = refls[r][0], r1 = refls[r][1];
            if (r == 2) { r0 = 1.0f / (1.0f + expf(-r0)); r1 = 1.0f / (1.0f + expf(-r1)); }
            else        { r0 = tanhf(r0); r1 = tanhf(r1); }
            float k1v = tanhf(r0);
            float k2v = tanhf(r1);
            float a1 = k1v * (1.0f - k2v);
            float a2 = fminf(0.999f, fmaxf(-0.999f, k2v));
            float bnd = 0.999f - fabsf(a2);
            a1 = fminf(bnd, fmaxf(-bnd, a1));
            float g = powf(1.0f / (1.0f + expf(-fbs[r][0])), 0.45f);
            int L = Ls[r];
            int idx = s_idx[r];
            sc1 = a1 * g;
            sc2 = a2 * g;
            sD1 = mind[r] + idx + 1;
            sD2 = mind[r] + ((idx + 1) % L) + 1;
            P[0][0] = sc1; P[0][1] = sc2;
        }
        __syncthreads();

        for (int cv = 0; cv < 9; cv++) {
            int d = plan[cv][0], a = plan[cv][1], bb = plan[cv][2];
            int la = psz[a], lb = psz[bb], ld = la + lb - 1;
            if (tid < ld) {
                int i = tid;
                int lo = i - (lb - 1); if (lo < 0) lo = 0;
                int hi = (la - 1 < i) ? la - 1 : i;
                float s = 0.0f;
                for (int q = lo; q <= hi; q++) s += P[a][q] * P[bb][i - q];
                // careful: in-place hazards avoided (dst always a new slot)
                P[d][i] = s;
            }
            __syncthreads();
        }

        if (tid == 0) {
            // pass j-sets and signs
            const int   js[4][3]  = {{1,2,3},{4,8,12},{16,32,48},{64,0,0}};
            const int   nj[4]     = {3, 3, 3, 1};
            // polynomial slot for power j
            // j:      1  2  3  4  8  12 16 32 48 64
            // slot:   0  1  2  3  4  5  6  7  8  9
            int D1 = sD1, D2 = sD2;
            for (int p = 0; p < 4; p++) {
                int ofs = 0, maxd = 0;
                for (int m = 0; m < nj[p]; m++) {
                    int j = js[p][m];
                    int slot;
                    switch (j) {
                        case 1: slot = 0; break; case 2: slot = 1; break;
                        case 3: slot = 2; break; case 4: slot = 3; break;
                        case 8: slot = 4; break; case 12: slot = 5; break;
                        case 16: slot = 6; break; case 32: slot = 7; break;
                        case 48: slot = 8; break; default: slot = 9; break;
                    }
                    float sgn = (j & 1) ? -1.0f : 1.0f;
                    for (int i = 0; i <= j; i++) {
                        int d = j * D1 + i * (D2 - D1);
                        g_pcoef[r][p][ofs] = sgn * P[slot][i];
                        g_pdel[r][p][ofs] = d;
                        if (d > maxd) maxd = d;
                        ofs++;
                    }
                }
                g_phalo[r][p] = (maxd + 511) & ~511;
            }
        }
        __syncthreads();
    }
}

// ------------------------------ noise -------------------------------
__global__ void noise_kernel(const float* __restrict__ nba,
                             const float* __restrict__ nb)
{
    int b = blockIdx.y;
    int t = blockIdx.x * blockDim.x + threadIdx.x;
    float acc = 0.0f;
    #pragma unroll
    for (int n = 0; n < NBANDS; n++)
        acc = fmaf(nba[((size_t)(b * NBANDS + n)) * T_LEN + t],
                   nb[(size_t)n * T_LEN + t], acc);
    g_noise[(size_t)b * T_LEN + t] = acc;
}

// ------------------------------ main --------------------------------
__global__ void __launch_bounds__(256) main_kernel(
                            const float* __restrict__ amps,
                            const float* __restrict__ fm_in,
                            const float* __restrict__ cps,
                            const float* __restrict__ nps,
                            const float* __restrict__ npg_in,
                            const float* __restrict__ fng_in)
{
    int b = blockIdx.y;
    int z = blockIdx.z;               // 0: cylinders 0-3 -> bankA, 1: 4-7 -> bankB
    int t = blockIdx.x * blockDim.x + threadIdx.x;
    size_t bt = (size_t)b * T_LEN + t;

    float phase = g_phase[bt];
    float fm    = fm_in[bt];
    float noise = g_noise[bt];
    float npg   = npg_in[bt];
    float fng   = fng_in[bt];
    float na    = nps[((size_t)(b * 2)) * T_LEN + t];
    float nbv   = nps[((size_t)(b * 2 + 1)) * T_LEN + t];

    float nph  = fmodf(phase, TWO_PI_F);
    float nenv = (1.0f - __expf(-na * nph)) * __expf(-nbv * nph);
    float noise_bursts = noise * nenv * npg;
    float flow = noise * fng * 0.3f;
    float turb1 = 1.0f + noise * (npg + fng) * 0.7f;

    float bank = 4.0f * (noise_bursts + flow);

    #pragma unroll 1
    for (int c4 = 0; c4 < 4; c4++) {
        int c = z * 4 + c4;
        float ang = c_forder[c] * (TWO_PI_F / 8.0f);
        float cph = fmodf(phase + ang, TWO_PI_F);
        float hp  = __powf(cph * (1.0f / TWO_PI_F), fm) * TWO_PI_F;
        float sv, cv;
        sincosf(hp, &sv, &cv);
        float twoC = 2.0f * cv;

        const float* ap = amps + ((size_t)(b * NCHN + c) * NHARM) * T_LEN + t;
        float sm1 = 0.0f, scur = sv, acc = 0.0f;
        #pragma unroll
        for (int h = 0; h < NHARM; h++) {
            acc = fmaf(__ldcs(ap + (size_t)h * T_LEN), scur, acc);
            float snxt = fmaf(twoC, scur, -sm1);
            sm1 = scur; scur = snxt;
        }
        float harm = -acc;

        float alpha = cps[((size_t)(b * 16 + c)) * T_LEN + t];
        float beta  = cps[((size_t)(b * 16 + 8 + c)) * T_LEN + t];
        float env = (1.0f - __expf(-alpha * cph)) * __expf(-beta * cph);
        bank = fmaf(harm * env * 10.0f, turb1, bank);
    }

    g_v0[((size_t)(b * 2 + z)) * T_LEN + t] = bank;
}

// -------------------------- FIR (smem-tiled) ------------------------
// chainmode 0: rows=4, chain=row&1, plain input rows
// chainmode 1: rows=2, chain=2; if pass==0, input = in[2*row] + in[2*row+1]
__global__ void __launch_bounds__(FIR_THREADS) fir_pass_kernel(
    const float* __restrict__ in, float* __restrict__ out,
    int pass, int chainmode)
{
    __shared__ float sx[HALOMAX + CHUNK];
    __shared__ float sc[MAXTAPS];
    __shared__ int   sd[MAXTAPS];

    int tid = threadIdx.x;
    int row = blockIdx.y;
    int chain = chainmode ? 2 : (row & 1);
    int cnt = c_pcnt[pass];
    int halo = g_phalo[chain][pass];

    for (int i = tid; i < cnt; i += FIR_THREADS) {
        sc[i] = g_pcoef[chain][pass][i];
        sd[i] = g_pdel[chain][pass][i];
    }

    int base = blockIdx.x * CHUNK;
    int nload = halo + CHUNK;
    if (chainmode && pass == 0) {
        const float* xa = in + ((size_t)(2 * row)) * T_LEN;
        const float* xb = in + ((size_t)(2 * row + 1)) * T_LEN;
        for (int k = tid; k < nload; k += FIR_THREADS) {
            int g = base - halo + k;
            sx[k] = (g >= 0) ? (xa[g] + xb[g]) : 0.0f;
        }
    } else {
        const float* x = in + (size_t)row * T_LEN;
        for (int k = tid; k < nload; k += FIR_THREADS) {
            int g = base - halo + k;
            sx[k] = (g >= 0) ? x[g] : 0.0f;
        }
    }
    __syncthreads();

    #pragma unroll
    for (int o = 0; o < CHUNK / FIR_THREADS; o++) {
        int li = o * FIR_THREADS + tid;       // local output index in chunk
        float acc = sx[halo + li];
        for (int i = 0; i < cnt; i++)
            acc = fmaf(sc[i], sx[halo + li - sd[i]], acc);
        out[(size_t)row * T_LEN + base + li] = acc;
    }
}

// ----------------------------- launch -------------------------------
extern "C" void kernel_launch(void* const* d_in, const int* in_sizes, int n_in,
                              void* d_out, int out_size)
{
    (void)in_sizes; (void)n_in; (void)out_size;
    const float* f0   = (const float*)d_in[0];
    const float* amps = (const float*)d_in[1];
    const float* fm   = (const float*)d_in[2];
    const float* cps  = (const float*)d_in[4];
    const float* nba  = (const float*)d_in[5];
    const float* nps  = (const float*)d_in[6];
    const float* npg  = (const float*)d_in[7];
    const float* fng  = (const float*)d_in[8];
    const float* nb   = (const float*)d_in[9];
    float* out = (float*)d_out;

    prep_kernel<<<3, 1024>>>(f0,
        (const float*)d_in[10], (const float*)d_in[11], (const float*)d_in[12],
        (const float*)d_in[13], (const float*)d_in[14], (const float*)d_in[15],
        (const float*)d_in[16], (const float*)d_in[17], (const float*)d_in[18]);

    dim3 g2(T_LEN / 256, 2);
    noise_kernel<<<g2, 256>>>(nba, nb);

    dim3 gm(T_LEN / 256, 2, 2);
    main_kernel<<<gm, 256>>>(amps, fm, cps, nps, npg, fng);

    float *v0, *v1, *vc0, *vc1;
    cudaGetSymbolAddress((void**)&v0, g_v0);
    cudaGetSymbolAddress((void**)&v1, g_v1);
    cudaGetSymbolAddress((void**)&vc0, g_vc0);
    cudaGetSymbolAddress((void**)&vc1, g_vc1);

    // chains a,b: 4 rows, 4 passes  v0 -> v1 -> v0 -> v1 -> v0
    dim3 gab(T_LEN / CHUNK, 4);
    fir_pass_kernel<<<gab, FIR_THREADS>>>(v0, v1, 0, 0);
    fir_pass_kernel<<<gab, FIR_THREADS>>>(v1, v0, 1, 0);
    fir_pass_kernel<<<gab, FIR_THREADS>>>(v0, v1, 2, 0);
    fir_pass_kernel<<<gab, FIR_THREADS>>>(v1, v0, 3, 0);

    // chain c: 2 rows, pass0 fuses the pairwise sum; last pass writes d_out
    dim3 gc(T_LEN / CHUNK, 2);
    fir_pass_kernel<<<gc, FIR_THREADS>>>(v0, vc0, 0, 1);
    fir_pass_kernel<<<gc, FIR_THREADS>>>(vc0, vc1, 1, 1);
    fir_pass_kernel<<<gc, FIR_THREADS>>>(vc1, vc0, 2, 1);
    fir_pass_kernel<<<gc, FIR_THREADS>>>(vc0, out, 3, 1);
}

// round 6
// speedup vs baseline: 1.6047x; 1.2473x over previous
#include <cuda_runtime.h>
#include <math.h>
#include <stdint.h>

// ====================================================================
// PulseTrainSynth — R5
//   prep  -> phase scan (blocks 0,1; fp32 inner + fp64 cross-thread)
//            + resonator setup (block 2) + noise dot (blocks 3..130)
//   main  -> harmonic bank, grid.z splits cylinders 0-3 / 4-7
//   reso  -> ALL 8 FIR passes + combine in one persistent kernel with
//            a software grid barrier (radix-4 Neumann factorization)
// ====================================================================

#define T_LEN 65536
#define NCHN 8
#define NHARM 64
#define NBANDS 32
#define TWO_PI_F 6.283185307179586f

#define CHUNK 2048
#define HALOMAX 8192
#define RES_THREADS 512
#define RES_BLOCKS 128
#define MAXTAPS 100

__device__ float g_phase[2 * T_LEN];
__device__ float g_noise[2 * T_LEN];
__device__ float g_v0[4 * T_LEN];
__device__ float g_v1[4 * T_LEN];
__device__ float g_vc0[2 * T_LEN];
__device__ float g_vc1[2 * T_LEN];

// pass tables: [chain][pass][tap]
__device__ float g_pcoef[3][4][MAXTAPS];
__device__ int   g_pdel[3][4][MAXTAPS];
__device__ int   g_phalo[3][4];

// software grid barrier state
__device__ unsigned g_bar_count = 0;
__device__ unsigned g_bar_gen   = 0;

__constant__ int   c_pcnt[4] = {9, 27, 99, 65};
__constant__ float c_forder[8] = {0.f, 4.f, 3.f, 7.f, 5.f, 2.f, 6.f, 1.f};

// ------------------------- threefry2x32-20 --------------------------
__device__ __forceinline__ void threefry2x32(uint32_t k0, uint32_t k1,
                                             uint32_t c0, uint32_t c1,
                                             uint32_t* o0, uint32_t* o1)
{
    uint32_t ks2 = k0 ^ k1 ^ 0x1BD11BDAu;
    uint32_t x0 = c0 + k0;
    uint32_t x1 = c1 + k1;
#define TF_R(r) { x0 += x1; x1 = (x1 << (r)) | (x1 >> (32 - (r))); x1 ^= x0; }
    TF_R(13) TF_R(15) TF_R(26) TF_R(6)   x0 += k1;  x1 += ks2 + 1u;
    TF_R(17) TF_R(29) TF_R(16) TF_R(24)  x0 += ks2; x1 += k0 + 2u;
    TF_R(13) TF_R(15) TF_R(26) TF_R(6)   x0 += k0;  x1 += k1 + 3u;
    TF_R(17) TF_R(29) TF_R(16) TF_R(24)  x0 += k1;  x1 += ks2 + 4u;
    TF_R(13) TF_R(15) TF_R(26) TF_R(6)   x0 += ks2; x1 += k0 + 5u;
#undef TF_R
    *o0 = x0; *o1 = x1;
}

__device__ __forceinline__ float jax_gumbel(uint32_t k0, uint32_t k1, int i)
{
    uint32_t o0, o1;
    threefry2x32(k0, k1, 0u, (uint32_t)i, &o0, &o1);
    uint32_t bits = o0 ^ o1;
    float f = __uint_as_float((bits >> 9) | 0x3F800000u) - 1.0f;  // [0,1)
    const float tiny = 1.17549435e-38f;
    float u = fmaxf(tiny, f);
    return -logf(-logf(u));
}

// --------------- prep: scan + setup + noise (one grid) --------------
__global__ void __launch_bounds__(1024) prep_kernel(const float* __restrict__ f0,
    const float* __restrict__ nba, const float* __restrict__ nb,
    const float* __restrict__ logit_a, const float* __restrict__ fbg_a, const float* __restrict__ refl_a,
    const float* __restrict__ logit_b, const float* __restrict__ fbg_b, const float* __restrict__ refl_b,
    const float* __restrict__ logit_c, const float* __restrict__ fbg_c, const float* __restrict__ refl_c)
{
    int tid = threadIdx.x;               // 1024 threads
    int lane = tid & 31, wid = tid >> 5;

    if (blockIdx.x >= 3) {
        // ------------------------ noise dot -------------------------
        int nbid = blockIdx.x - 3;          // 0..127
        int b = nbid >> 6;                  // 64 blocks per batch
        int t = (nbid & 63) * 1024 + tid;
        float acc = 0.0f;
        #pragma unroll
        for (int n = 0; n < NBANDS; n++)
            acc = fmaf(nba[((size_t)(b * NBANDS + n)) * T_LEN + t],
                       nb[(size_t)n * T_LEN + t], acc);
        g_noise[(size_t)b * T_LEN + t] = acc;
        return;
    }

    if (blockIdx.x < 2) {
        // ----- phase prefix sum: fp32 inner, fp64 cross-thread -----
        int b = blockIdx.x;
        const float* f = f0 + (size_t)b * T_LEN;
        const int base = tid * 64;
        float zf[64];
        float s = 0.0f;
        #pragma unroll
        for (int i = 0; i < 64; i++) {
            zf[i] = (TWO_PI_F * f[base + i]) / 48000.0f;
            s += zf[i];
        }
        double inc = (double)s;
        #pragma unroll
        for (int off = 1; off < 32; off <<= 1) {
            double nv = __shfl_up_sync(0xffffffffu, inc, off);
            if (lane >= off) inc += nv;
        }
        __shared__ double wsums[32];
        if (lane == 31) wsums[wid] = inc;
        __syncthreads();
        if (wid == 0) {
            double w = wsums[lane];
            #pragma unroll
            for (int off = 1; off < 32; off <<= 1) {
                double nv = __shfl_up_sync(0xffffffffu, w, off);
                if (lane >= off) w += nv;
            }
            wsums[lane] = w;
        }
        __syncthreads();
        double base_d = inc - (double)s + (wid ? wsums[wid - 1] : 0.0); // exclusive
        float base_half = (float)(0.5 * base_d);
        float run = 0.0f;
        #pragma unroll
        for (int i = 0; i < 64; i++) {
            run += zf[i];
            g_phase[(size_t)b * T_LEN + base + i] = fmaf(0.5f, run, base_half);
        }
        return;
    }

    // ------------------------- setup (block 2) ----------------------
    __shared__ uint32_t skey[3][2];
    __shared__ float rv[128];
    __shared__ int   ri[128];
    __shared__ int   s_idx[3];
    __shared__ float sc1, sc2;
    __shared__ int   sD1, sD2;
    __shared__ float P[10][65];   // A^1,A^2,A^3,A^4,A^8,A^12,A^16,A^32,A^48,A^64

    if (tid == 0) {
        for (int j = 0; j < 3; j++) {
            uint32_t o0, o1;
            threefry2x32(0u, 42u, 0u, (uint32_t)j, &o0, &o1);
            skey[j][0] = o0; skey[j][1] = o1;
        }
    }
    __syncthreads();

    const float* logits[3] = {logit_a, logit_b, logit_c};
    const float* refls[3]  = {refl_a, refl_b, refl_c};
    const float* fbs[3]    = {fbg_a, fbg_b, fbg_c};
    const int    Ls[3]     = {85, 85, 8};
    const int    mind[3]   = {40, 40, 32};

    for (int r = 0; r < 3; r++) {
        int L = Ls[r];
        if (tid < 128) {
            float score = -3.0e38f;
            if (tid < L)
                score = logits[r][tid] + jax_gumbel(skey[r][0], skey[r][1], tid);
            rv[tid] = score; ri[tid] = tid;
        }
        __syncthreads();
        for (int s = 64; s > 0; s >>= 1) {
            if (tid < s) {
                float ov = rv[tid + s]; int oi = ri[tid + s];
                if (ov > rv[tid] || (ov == rv[tid] && oi < ri[tid])) {
                    rv[tid] = ov; ri[tid] = oi;
                }
            }
            __syncthreads();
        }
        if (tid == 0) s_idx[r] = ri[0];
        __syncthreads();
    }

    const int psz[10] = {2, 3, 4, 5, 9, 13, 17, 33, 49, 65};
    const int plan[9][3] = {
        {1, 0, 0}, {2, 0, 1}, {3, 1, 1}, {4, 3, 3}, {5, 3, 4},
        {6, 4, 4}, {7, 6, 6}, {8, 6, 7}, {9, 7, 7},
    };

    for (int r = 0; r < 3; r++) {
        if (tid == 0) {
            float r0 = refls[r][0], r1 = refls[r][1];
            if (r == 2) { r0 = 1.0f / (1.0f + expf(-r0)); r1 = 1.0f / (1.0f + expf(-r1)); }
            else        { r0 = tanhf(r0); r1 = tanhf(r1); }
            float k1v = tanhf(r0);
            float k2v = tanhf(r1);
            float a1 = k1v * (1.0f - k2v);
            float a2 = fminf(0.999f, fmaxf(-0.999f, k2v));
            float bnd = 0.999f - fabsf(a2);
            a1 = fminf(bnd, fmaxf(-bnd, a1));
            float g = powf(1.0f / (1.0f + expf(-fbs[r][0])), 0.45f);
            int L = Ls[r];
            int idx = s_idx[r];
            sc1 = a1 * g;
            sc2 = a2 * g;
            sD1 = mind[r] + idx + 1;
            sD2 = mind[r] + ((idx + 1) % L) + 1;
            P[0][0] = sc1; P[0][1] = sc2;
        }
        __syncthreads();

        for (int cv = 0; cv < 9; cv++) {
            int d = plan[cv][0], a = plan[cv][1], bb = plan[cv][2];
            int la = psz[a], lb = psz[bb], ld = la + lb - 1;
            if (tid < ld) {
                int i = tid;
                int lo = i - (lb - 1); if (lo < 0) lo = 0;
                int hi = (la - 1 < i) ? la - 1 : i;
                float s = 0.0f;
                for (int q = lo; q <= hi; q++) s += P[a][q] * P[bb][i - q];
                P[d][i] = s;
            }
            __syncthreads();
        }

        if (tid == 0) {
            const int js[4][3] = {{1,2,3},{4,8,12},{16,32,48},{64,0,0}};
            const int nj[4]    = {3, 3, 3, 1};
            int D1 = sD1, D2 = sD2;
            for (int p = 0; p < 4; p++) {
                int ofs = 0, maxd = 0;
                for (int m = 0; m < nj[p]; m++) {
                    int j = js[p][m];
                    int slot;
                    switch (j) {
                        case 1: slot = 0; break; case 2: slot = 1; break;
                        case 3: slot = 2; break; case 4: slot = 3; break;
                        case 8: slot = 4; break; case 12: slot = 5; break;
                        case 16: slot = 6; break; case 32: slot = 7; break;
                        case 48: slot = 8; break; default: slot = 9; break;
                    }
                    float sgn = (j & 1) ? -1.0f : 1.0f;
                    for (int i = 0; i <= j; i++) {
                        int d = j * D1 + i * (D2 - D1);
                        g_pcoef[r][p][ofs] = sgn * P[slot][i];
                        g_pdel[r][p][ofs] = d;
                        if (d > maxd) maxd = d;
                        ofs++;
                    }
                }
                g_phalo[r][p] = (maxd + 511) & ~511;
            }
        }
        __syncthreads();
    }
}

// ------------------------------ main --------------------------------
__global__ void __launch_bounds__(256) main_kernel(
                            const float* __restrict__ amps,
                            const float* __restrict__ fm_in,
                            const float* __restrict__ cps,
                            const float* __restrict__ nps,
                            const float* __restrict__ npg_in,
                            const float* __restrict__ fng_in)
{
    int b = blockIdx.y;
    int z = blockIdx.z;               // 0: cylinders 0-3 -> bankA, 1: 4-7 -> bankB
    int t = blockIdx.x * blockDim.x + threadIdx.x;
    size_t bt = (size_t)b * T_LEN + t;

    float phase = g_phase[bt];
    float fm    = fm_in[bt];
    float noise = g_noise[bt];
    float npg   = npg_in[bt];
    float fng   = fng_in[bt];
    float na    = nps[((size_t)(b * 2)) * T_LEN + t];
    float nbv   = nps[((size_t)(b * 2 + 1)) * T_LEN + t];

    float nph  = fmodf(phase, TWO_PI_F);
    float nenv = (1.0f - __expf(-na * nph)) * __expf(-nbv * nph);
    float noise_bursts = noise * nenv * npg;
    float flow = noise * fng * 0.3f;
    float turb1 = 1.0f + noise * (npg + fng) * 0.7f;

    float bank = 4.0f * (noise_bursts + flow);

    #pragma unroll 1
    for (int c4 = 0; c4 < 4; c4++) {
        int c = z * 4 + c4;
        float ang = c_forder[c] * (TWO_PI_F / 8.0f);
        float cph = fmodf(phase + ang, TWO_PI_F);
        float hp  = __powf(cph * (1.0f / TWO_PI_F), fm) * TWO_PI_F;
        float sv, cv;
        sincosf(hp, &sv, &cv);
        float twoC = 2.0f * cv;

        const float* ap = amps + ((size_t)(b * NCHN + c) * NHARM) * T_LEN + t;
        float sm1 = 0.0f, scur = sv, acc = 0.0f;
        #pragma unroll
        for (int h = 0; h < NHARM; h++) {
            acc = fmaf(__ldcs(ap + (size_t)h * T_LEN), scur, acc);
            float snxt = fmaf(twoC, scur, -sm1);
            sm1 = scur; scur = snxt;
        }
        float harm = -acc;

        float alpha = cps[((size_t)(b * 16 + c)) * T_LEN + t];
        float beta  = cps[((size_t)(b * 16 + 8 + c)) * T_LEN + t];
        float env = (1.0f - __expf(-alpha * cph)) * __expf(-beta * cph);
        bank = fmaf(harm * env * 10.0f, turb1, bank);
    }

    g_v0[((size_t)(b * 2 + z)) * T_LEN + t] = bank;
}

// ---------------- resonator: all passes, one kernel -----------------
__device__ __forceinline__ void grid_barrier()
{
    __syncthreads();
    if (threadIdx.x == 0) {
        __threadfence();
        unsigned gen = *((volatile unsigned*)&g_bar_gen);
        if (atomicAdd(&g_bar_count, 1u) == (unsigned)(RES_BLOCKS - 1)) {
            atomicExch(&g_bar_count, 0u);
            __threadfence();
            atomicAdd(&g_bar_gen, 1u);
        } else {
            while (*((volatile unsigned*)&g_bar_gen) == gen) __nanosleep(64);
        }
        __threadfence();
    }
    __syncthreads();
}

__device__ __forceinline__ void fir_stage(
    const float* __restrict__ in, float* __restrict__ out,
    int row, int chunk, int chain, int pass, int sumpair,
    float* sx, float* sc, int* sd)
{
    int tid = threadIdx.x;
    int cnt = c_pcnt[pass];
    int halo = g_phalo[chain][pass];

    for (int i = tid; i < cnt; i += RES_THREADS) {
        sc[i] = g_pcoef[chain][pass][i];
        sd[i] = g_pdel[chain][pass][i];
    }

    int base = chunk * CHUNK;
    int nload = halo + CHUNK;
    if (sumpair) {
        const float* xa = in + ((size_t)(2 * row)) * T_LEN;
        const float* xb = in + ((size_t)(2 * row + 1)) * T_LEN;
        for (int k = tid; k < nload; k += RES_THREADS) {
            int g = base - halo + k;
            sx[k] = (g >= 0) ? (xa[g] + xb[g]) : 0.0f;
        }
    } else {
        const float* x = in + (size_t)row * T_LEN;
        for (int k = tid; k < nload; k += RES_THREADS) {
            int g = base - halo + k;
            sx[k] = (g >= 0) ? x[g] : 0.0f;
        }
    }
    __syncthreads();

    #pragma unroll
    for (int o = 0; o < CHUNK / RES_THREADS; o++) {
        int li = o * RES_THREADS + tid;
        float acc = sx[halo + li];
        for (int i = 0; i < cnt; i++)
            acc = fmaf(sc[i], sx[halo + li - sd[i]], acc);
        out[(size_t)row * T_LEN + base + li] = acc;
    }
}

__global__ void __launch_bounds__(RES_THREADS) resonator_kernel(float* __restrict__ out)
{
    __shared__ float sx[HALOMAX + CHUNK];
    __shared__ float sc[MAXTAPS];
    __shared__ int   sd[MAXTAPS];

    int bid = blockIdx.x;                 // 0..127
    int row4 = bid >> 5;                  // 0..3
    int chunk = bid & 31;                 // 0..31
    int chain_ab = row4 & 1;

    // chains a,b: 4 passes, v0 -> v1 -> v0 -> v1 -> v0
    fir_stage(g_v0, g_v1, row4, chunk, chain_ab, 0, 0, sx, sc, sd);
    grid_barrier();
    fir_stage(g_v1, g_v0, row4, chunk, chain_ab, 1, 0, sx, sc, sd);
    grid_barrier();
    fir_stage(g_v0, g_v1, row4, chunk, chain_ab, 2, 0, sx, sc, sd);
    grid_barrier();
    fir_stage(g_v1, g_v0, row4, chunk, chain_ab, 3, 0, sx, sc, sd);
    grid_barrier();

    // chain c: 2 rows; pass0 fuses the pairwise sum of v0 rows
    int active = (bid < 64);
    int rowc = bid >> 5;                  // 0..1 for active blocks
    if (active) fir_stage(g_v0, g_vc0, rowc, chunk, 2, 0, 1, sx, sc, sd);
    grid_barrier();
    if (active) fir_stage(g_vc0, g_vc1, rowc, chunk, 2, 1, 0, sx, sc, sd);
    grid_barrier();
    if (active) fir_stage(g_vc1, g_vc0, rowc, chunk, 2, 2, 0, sx, sc, sd);
    grid_barrier();
    if (active) fir_stage(g_vc0, out, rowc, chunk, 2, 3, 0, sx, sc, sd);
}

// ----------------------------- launch -------------------------------
extern "C" void kernel_launch(void* const* d_in, const int* in_sizes, int n_in,
                              void* d_out, int out_size)
{
    (void)in_sizes; (void)n_in; (void)out_size;
    const float* f0   = (const float*)d_in[0];
    const float* amps = (const float*)d_in[1];
    const float* fm   = (const float*)d_in[2];
    const float* cps  = (const float*)d_in[4];
    const float* nba  = (const float*)d_in[5];
    const float* nps  = (const float*)d_in[6];
    const float* npg  = (const float*)d_in[7];
    const float* fng  = (const float*)d_in[8];
    const float* nb   = (const float*)d_in[9];
    float* out = (float*)d_out;

    prep_kernel<<<131, 1024>>>(f0, nba, nb,
        (const float*)d_in[10], (const float*)d_in[11], (const float*)d_in[12],
        (const float*)d_in[13], (const float*)d_in[14], (const float*)d_in[15],
        (const float*)d_in[16], (const float*)d_in[17], (const float*)d_in[18]);

    dim3 gm(T_LEN / 256, 2, 2);
    main_kernel<<<gm, 256>>>(amps, fm, cps, nps, npg, fng);

    resonator_kernel<<<RES_BLOCKS, RES_THREADS>>>(out);
}

// round 7
// speedup vs baseline: 1.9568x; 1.2194x over previous
#include <cuda_runtime.h>
#include <math.h>
#include <stdint.h>

// ====================================================================
// PulseTrainSynth — R6
//   prep  -> scan (blocks 0,1, no-spill float4) + setup (block 2,
//            parallel tap fill) + noise dot (blocks 3..34, float4)
//   main  -> harmonic bank, ILP-2 (two time samples per thread)
//   reso  -> persistent kernel, 8 FIR passes, software grid barrier
// ====================================================================

#define T_LEN 65536
#define NCHN 8
#define NHARM 64
#define NBANDS 32
#define TWO_PI_F 6.283185307179586f

#define CHUNK 2048
#define HALOMAX 8192
#define RES_THREADS 512
#define RES_BLOCKS 128
#define MAXTAPS 100

__device__ float g_phase[2 * T_LEN];
__device__ float g_noise[2 * T_LEN];
__device__ float g_v0[4 * T_LEN];
__device__ float g_v1[4 * T_LEN];
__device__ float g_vc0[2 * T_LEN];
__device__ float g_vc1[2 * T_LEN];

__device__ float g_pcoef[3][4][MAXTAPS];
__device__ int   g_pdel[3][4][MAXTAPS];
__device__ int   g_phalo[3][4];

__device__ unsigned g_bar_count = 0;
__device__ unsigned g_bar_gen   = 0;

__constant__ int   c_pcnt[4] = {9, 27, 99, 65};
__constant__ float c_forder[8] = {0.f, 4.f, 3.f, 7.f, 5.f, 2.f, 6.f, 1.f};

// ------------------------- threefry2x32-20 --------------------------
__device__ __forceinline__ void threefry2x32(uint32_t k0, uint32_t k1,
                                             uint32_t c0, uint32_t c1,
                                             uint32_t* o0, uint32_t* o1)
{
    uint32_t ks2 = k0 ^ k1 ^ 0x1BD11BDAu;
    uint32_t x0 = c0 + k0;
    uint32_t x1 = c1 + k1;
#define TF_R(r) { x0 += x1; x1 = (x1 << (r)) | (x1 >> (32 - (r))); x1 ^= x0; }
    TF_R(13) TF_R(15) TF_R(26) TF_R(6)   x0 += k1;  x1 += ks2 + 1u;
    TF_R(17) TF_R(29) TF_R(16) TF_R(24)  x0 += ks2; x1 += k0 + 2u;
    TF_R(13) TF_R(15) TF_R(26) TF_R(6)   x0 += k0;  x1 += k1 + 3u;
    TF_R(17) TF_R(29) TF_R(16) TF_R(24)  x0 += k1;  x1 += ks2 + 4u;
    TF_R(13) TF_R(15) TF_R(26) TF_R(6)   x0 += ks2; x1 += k0 + 5u;
#undef TF_R
    *o0 = x0; *o1 = x1;
}

__device__ __forceinline__ float jax_gumbel(uint32_t k0, uint32_t k1, int i)
{
    uint32_t o0, o1;
    threefry2x32(k0, k1, 0u, (uint32_t)i, &o0, &o1);
    uint32_t bits = o0 ^ o1;
    float f = __uint_as_float((bits >> 9) | 0x3F800000u) - 1.0f;  // [0,1)
    const float tiny = 1.17549435e-38f;
    float u = fmaxf(tiny, f);
    return -logf(-logf(u));
}

// --------------- prep: scan + setup + noise (one grid) --------------
__global__ void __launch_bounds__(1024) prep_kernel(const float* __restrict__ f0,
    const float* __restrict__ nba, const float* __restrict__ nb,
    const float* __restrict__ logit_a, const float* __restrict__ fbg_a, const float* __restrict__ refl_a,
    const float* __restrict__ logit_b, const float* __restrict__ fbg_b, const float* __restrict__ refl_b,
    const float* __restrict__ logit_c, const float* __restrict__ fbg_c, const float* __restrict__ refl_c)
{
    int tid = threadIdx.x;               // 1024 threads
    int lane = tid & 31, wid = tid >> 5;

    if (blockIdx.x >= 3) {
        // ---------------- noise dot (float4, 1 out/thread) ----------
        int v4 = (blockIdx.x - 3) * 1024 + tid;     // 0..32767
        int b  = v4 >> 14;
        int tq = v4 & 16383;
        const float4* nba4 = (const float4*)nba;
        const float4* nb4  = (const float4*)nb;
        float4 acc = make_float4(0.f, 0.f, 0.f, 0.f);
        #pragma unroll
        for (int n = 0; n < NBANDS; n++) {
            float4 a = nba4[((size_t)(b * NBANDS + n) * T_LEN >> 2) + tq];
            float4 w = nb4[((size_t)n * T_LEN >> 2) + tq];
            acc.x = fmaf(a.x, w.x, acc.x);
            acc.y = fmaf(a.y, w.y, acc.y);
            acc.z = fmaf(a.z, w.z, acc.z);
            acc.w = fmaf(a.w, w.w, acc.w);
        }
        ((float4*)g_noise)[((size_t)b * T_LEN >> 2) + tq] = acc;
        return;
    }

    if (blockIdx.x < 2) {
        // ----- phase prefix sum: fp32 inner (reload), fp64 cross ----
        int b = blockIdx.x;
        const float4* f4 = (const float4*)(f0 + (size_t)b * T_LEN);
        const int vbase = tid * 16;              // 16 float4 = 64 floats
        float s = 0.0f;
        #pragma unroll
        for (int i = 0; i < 16; i++) {
            float4 v = f4[vbase + i];
            float c = (TWO_PI_F / 48000.0f);
            s += (TWO_PI_F * v.x) / 48000.0f;
            s += (TWO_PI_F * v.y) / 48000.0f;
            s += (TWO_PI_F * v.z) / 48000.0f;
            s += (TWO_PI_F * v.w) / 48000.0f;
            (void)c;
        }
        double inc = (double)s;
        #pragma unroll
        for (int off = 1; off < 32; off <<= 1) {
            double nv = __shfl_up_sync(0xffffffffu, inc, off);
            if (lane >= off) inc += nv;
        }
        __shared__ double wsums[32];
        if (lane == 31) wsums[wid] = inc;
        __syncthreads();
        if (wid == 0) {
            double w = wsums[lane];
            #pragma unroll
            for (int off = 1; off < 32; off <<= 1) {
                double nv = __shfl_up_sync(0xffffffffu, w, off);
                if (lane >= off) w += nv;
            }
            wsums[lane] = w;
        }
        __syncthreads();
        double base_d = inc - (double)s + (wid ? wsums[wid - 1] : 0.0); // exclusive
        float base_half = (float)(0.5 * base_d);
        float4* ph4 = (float4*)(g_phase + (size_t)b * T_LEN);
        float run = 0.0f;
        #pragma unroll
        for (int i = 0; i < 16; i++) {
            float4 v = f4[vbase + i];
            float p0 = run + (TWO_PI_F * v.x) / 48000.0f;
            float p1 = p0  + (TWO_PI_F * v.y) / 48000.0f;
            float p2 = p1  + (TWO_PI_F * v.z) / 48000.0f;
            float p3 = p2  + (TWO_PI_F * v.w) / 48000.0f;
            run = p3;
            float4 o;
            o.x = fmaf(0.5f, p0, base_half);
            o.y = fmaf(0.5f, p1, base_half);
            o.z = fmaf(0.5f, p2, base_half);
            o.w = fmaf(0.5f, p3, base_half);
            ph4[vbase + i] = o;
        }
        return;
    }

    // ------------------------- setup (block 2) ----------------------
    __shared__ uint32_t skey[3][2];
    __shared__ float rv[128];
    __shared__ int   ri[128];
    __shared__ int   s_idx[3];
    __shared__ int   sD1, sD2;
    __shared__ float P[10][65];   // A^1,A^2,A^3,A^4,A^8,A^12,A^16,A^32,A^48,A^64

    if (tid == 0) {
        for (int j = 0; j < 3; j++) {
            uint32_t o0, o1;
            threefry2x32(0u, 42u, 0u, (uint32_t)j, &o0, &o1);
            skey[j][0] = o0; skey[j][1] = o1;
        }
    }
    __syncthreads();

    const float* logits[3] = {logit_a, logit_b, logit_c};
    const float* refls[3]  = {refl_a, refl_b, refl_c};
    const float* fbs[3]    = {fbg_a, fbg_b, fbg_c};
    const int    Ls[3]     = {85, 85, 8};
    const int    mind[3]   = {40, 40, 32};

    for (int r = 0; r < 3; r++) {
        int L = Ls[r];
        if (tid < 128) {
            float score = -3.0e38f;
            if (tid < L)
                score = logits[r][tid] + jax_gumbel(skey[r][0], skey[r][1], tid);
            rv[tid] = score; ri[tid] = tid;
        }
        __syncthreads();
        for (int s = 64; s > 0; s >>= 1) {
            if (tid < s) {
                float ov = rv[tid + s]; int oi = ri[tid + s];
                if (ov > rv[tid] || (ov == rv[tid] && oi < ri[tid])) {
                    rv[tid] = ov; ri[tid] = oi;
                }
            }
            __syncthreads();
        }
        if (tid == 0) s_idx[r] = ri[0];
        __syncthreads();
    }

    const int psz[10] = {2, 3, 4, 5, 9, 13, 17, 33, 49, 65};
    const int plan[9][3] = {
        {1, 0, 0}, {2, 0, 1}, {3, 1, 1}, {4, 3, 3}, {5, 3, 4},
        {6, 4, 4}, {7, 6, 6}, {8, 6, 7}, {9, 7, 7},
    };
    const int js[4][3]      = {{1,2,3},{4,8,12},{16,32,48},{64,0,0}};
    const int nj[4]         = {3, 3, 3, 1};
    const int slotTab[4][3] = {{0,1,2},{3,4,5},{6,7,8},{9,9,9}};

    for (int r = 0; r < 3; r++) {
        if (tid == 0) {
            float r0 = refls[r][0], r1 = refls[r][1];
            if (r == 2) { r0 = 1.0f / (1.0f + expf(-r0)); r1 = 1.0f / (1.0f + expf(-r1)); }
            else        { r0 = tanhf(r0); r1 = tanhf(r1); }
            float k1v = tanhf(r0);
            float k2v = tanhf(r1);
            float a1 = k1v * (1.0f - k2v);
            float a2 = fminf(0.999f, fmaxf(-0.999f, k2v));
            float bnd = 0.999f - fabsf(a2);
            a1 = fminf(bnd, fmaxf(-bnd, a1));
            float g = powf(1.0f / (1.0f + expf(-fbs[r][0])), 0.45f);
            int L = Ls[r];
            int idx = s_idx[r];
            sD1 = mind[r] + idx + 1;
            sD2 = mind[r] + ((idx + 1) % L) + 1;
            P[0][0] = a1 * g; P[0][1] = a2 * g;
        }
        __syncthreads();

        for (int cv = 0; cv < 9; cv++) {
            int d = plan[cv][0], a = plan[cv][1], bb = plan[cv][2];
            int la = psz[a], lb = psz[bb], ld = la + lb - 1;
            if (tid < ld) {
                int i = tid;
                int lo = i - (lb - 1); if (lo < 0) lo = 0;
                int hi = (la - 1 < i) ? la - 1 : i;
                float s = 0.0f;
                for (int q = lo; q <= hi; q++) s += P[a][q] * P[bb][i - q];
                P[d][i] = s;
            }
            __syncthreads();
        }

        // ---- parallel tap-table fill (thread per tap) ----
        int D1 = sD1, D2 = sD2;
        #pragma unroll
        for (int p = 0; p < 4; p++) {
            int cnt = (p == 0) ? 9 : (p == 1 ? 27 : (p == 2 ? 99 : 65));
            if (tid < cnt) {
                int m = 0, bofs = 0;
                while (m < nj[p] - 1 && tid >= bofs + js[p][m] + 1) {
                    bofs += js[p][m] + 1; m++;
                }
                int j = js[p][m];
                int i = tid - bofs;
                float sgn = (j & 1) ? -1.0f : 1.0f;
                g_pcoef[r][p][tid] = sgn * P[slotTab[p][m]][i];
                g_pdel[r][p][tid]  = j * D1 + i * (D2 - D1);
            }
            if (tid == 0) {
                int jmax = js[p][nj[p] - 1];
                int maxD = (D1 > D2) ? D1 : D2;
                g_phalo[r][p] = (jmax * maxD + 511) & ~511;
            }
        }
        __syncthreads();
    }
}

// ------------------------------ main (ILP-2) ------------------------
__global__ void __launch_bounds__(256) main_kernel(
                            const float* __restrict__ amps,
                            const float* __restrict__ fm_in,
                            const float* __restrict__ cps,
                            const float* __restrict__ nps,
                            const float* __restrict__ npg_in,
                            const float* __restrict__ fng_in)
{
    int b = blockIdx.y;
    int z = blockIdx.z;               // 0: cylinders 0-3 -> bankA, 1: 4-7 -> bankB
    int t0 = blockIdx.x * 512 + threadIdx.x;   // second sample at t0+256
    size_t brow = (size_t)b * T_LEN;

    float bank[2], turb1[2], phase[2];
    #pragma unroll
    for (int u = 0; u < 2; u++) {
        int t = t0 + u * 256;
        size_t bt = brow + t;
        float ph    = g_phase[bt];
        float noise = g_noise[bt];
        float npg   = npg_in[bt];
        float fng   = fng_in[bt];
        float na    = nps[(size_t)(b * 2) * T_LEN + t];
        float nbv   = nps[(size_t)(b * 2 + 1) * T_LEN + t];
        float nph   = fmodf(ph, TWO_PI_F);
        float nenv  = (1.0f - __expf(-na * nph)) * __expf(-nbv * nph);
        bank[u]  = 4.0f * (noise * nenv * npg + noise * fng * 0.3f);
        turb1[u] = 1.0f + noise * (npg + fng) * 0.7f;
        phase[u] = ph;
    }

    #pragma unroll 1
    for (int c4 = 0; c4 < 4; c4++) {
        int c = z * 4 + c4;
        float ang = c_forder[c] * (TWO_PI_F / 8.0f);
        const float* ap = amps + ((size_t)(b * NCHN + c) * NHARM) * T_LEN + t0;

        float cph[2], scur[2], sm1[2], twoC[2], acc[2];
        #pragma unroll
        for (int u = 0; u < 2; u++) {
            float cp = fmodf(phase[u] + ang, TWO_PI_F);
            float fm = fm_in[brow + t0 + u * 256];
            float hp = __powf(cp * (1.0f / TWO_PI_F), fm) * TWO_PI_F;
            float sv, cv;
            sincosf(hp, &sv, &cv);
            cph[u] = cp; scur[u] = sv; sm1[u] = 0.0f;
            twoC[u] = 2.0f * cv; acc[u] = 0.0f;
        }

        #pragma unroll
        for (int h = 0; h < NHARM; h++) {
            #pragma unroll
            for (int u = 0; u < 2; u++) {
                acc[u] = fmaf(__ldcs(ap + (size_t)h * T_LEN + u * 256), scur[u], acc[u]);
                float snxt = fmaf(twoC[u], scur[u], -sm1[u]);
                sm1[u] = scur[u]; scur[u] = snxt;
            }
        }

        #pragma unroll
        for (int u = 0; u < 2; u++) {
            int t = t0 + u * 256;
            float alpha = cps[(size_t)(b * 16 + c) * T_LEN + t];
            float beta  = cps[(size_t)(b * 16 + 8 + c) * T_LEN + t];
            float env = (1.0f - __expf(-alpha * cph[u])) * __expf(-beta * cph[u]);
            bank[u] = fmaf(-acc[u] * env * 10.0f, turb1[u], bank[u]);
        }
    }

    #pragma unroll
    for (int u = 0; u < 2; u++)
        g_v0[(size_t)(b * 2 + z) * T_LEN + t0 + u * 256] = bank[u];
}

// ---------------- resonator: all passes, one kernel -----------------
__device__ __forceinline__ void grid_barrier()
{
    __syncthreads();
    if (threadIdx.x == 0) {
        __threadfence();
        unsigned gen = *((volatile unsigned*)&g_bar_gen);
        if (atomicAdd(&g_bar_count, 1u) == (unsigned)(RES_BLOCKS - 1)) {
            atomicExch(&g_bar_count, 0u);
            __threadfence();
            atomicAdd(&g_bar_gen, 1u);
        } else {
            while (*((volatile unsigned*)&g_bar_gen) == gen) __nanosleep(64);
        }
        __threadfence();
    }
    __syncthreads();
}

__device__ __forceinline__ void fir_stage(
    const float* __restrict__ in, float* __restrict__ out,
    int row, int chunk, int chain, int pass, int sumpair,
    float* sx, float* sc, int* sd)
{
    int tid = threadIdx.x;
    int cnt = c_pcnt[pass];
    int halo = g_phalo[chain][pass];

    for (int i = tid; i < cnt; i += RES_THREADS) {
        sc[i] = g_pcoef[chain][pass][i];
        sd[i] = g_pdel[chain][pass][i];
    }

    int base = chunk * CHUNK;
    int nload = halo + CHUNK;
    if (sumpair) {
        const float* xa = in + ((size_t)(2 * row)) * T_LEN;
        const float* xb = in + ((size_t)(2 * row + 1)) * T_LEN;
        for (int k = tid; k < nload; k += RES_THREADS) {
            int g = base - halo + k;
            sx[k] = (g >= 0) ? (xa[g] + xb[g]) : 0.0f;
        }
    } else {
        const float* x = in + (size_t)row * T_LEN;
        for (int k = tid; k < nload; k += RES_THREADS) {
            int g = base - halo + k;
            sx[k] = (g >= 0) ? x[g] : 0.0f;
        }
    }
    __syncthreads();

    #pragma unroll
    for (int o = 0; o < CHUNK / RES_THREADS; o++) {
        int li = o * RES_THREADS + tid;
        float acc = sx[halo + li];
        for (int i = 0; i < cnt; i++)
            acc = fmaf(sc[i], sx[halo + li - sd[i]], acc);
        out[(size_t)row * T_LEN + base + li] = acc;
    }
}

__global__ void __launch_bounds__(RES_THREADS) resonator_kernel(float* __restrict__ out)
{
    __shared__ float sx[HALOMAX + CHUNK];
    __shared__ float sc[MAXTAPS];
    __shared__ int   sd[MAXTAPS];

    int bid = blockIdx.x;                 // 0..127
    int row4 = bid >> 5;                  // 0..3
    int chunk = bid & 31;                 // 0..31
    int chain_ab = row4 & 1;

    fir_stage(g_v0, g_v1, row4, chunk, chain_ab, 0, 0, sx, sc, sd);
    grid_barrier();
    fir_stage(g_v1, g_v0, row4, chunk, chain_ab, 1, 0, sx, sc, sd);
    grid_barrier();
    fir_stage(g_v0, g_v1, row4, chunk, chain_ab, 2, 0, sx, sc, sd);
    grid_barrier();
    fir_stage(g_v1, g_v0, row4, chunk, chain_ab, 3, 0, sx, sc, sd);
    grid_barrier();

    int active = (bid < 64);
    int rowc = bid >> 5;
    if (active) fir_stage(g_v0, g_vc0, rowc, chunk, 2, 0, 1, sx, sc, sd);
    grid_barrier();
    if (active) fir_stage(g_vc0, g_vc1, rowc, chunk, 2, 1, 0, sx, sc, sd);
    grid_barrier();
    if (active) fir_stage(g_vc1, g_vc0, rowc, chunk, 2, 2, 0, sx, sc, sd);
    grid_barrier();
    if (active) fir_stage(g_vc0, out, rowc, chunk, 2, 3, 0, sx, sc, sd);
}

// ----------------------------- launch -------------------------------
extern "C" void kernel_launch(void* const* d_in, const int* in_sizes, int n_in,
                              void* d_out, int out_size)
{
    (void)in_sizes; (void)n_in; (void)out_size;
    const float* f0   = (const float*)d_in[0];
    const float* amps = (const float*)d_in[1];
    const float* fm   = (const float*)d_in[2];
    const float* cps  = (const float*)d_in[4];
    const float* nba  = (const float*)d_in[5];
    const float* nps  = (const float*)d_in[6];
    const float* npg  = (const float*)d_in[7];
    const float* fng  = (const float*)d_in[8];
    const float* nb   = (const float*)d_in[9];
    float* out = (float*)d_out;

    prep_kernel<<<35, 1024>>>(f0, nba, nb,
        (const float*)d_in[10], (const float*)d_in[11], (const float*)d_in[12],
        (const float*)d_in[13], (const float*)d_in[14], (const float*)d_in[15],
        (const float*)d_in[16], (const float*)d_in[17], (const float*)d_in[18]);

    dim3 gm(T_LEN / 512, 2, 2);
    main_kernel<<<gm, 256>>>(amps, fm, cps, nps, npg, fng);

    resonator_kernel<<<RES_BLOCKS, RES_THREADS>>>(out);
}